// round 14
// baseline (speedup 1.0000x reference)
#include <cuda_runtime.h>
#include <math.h>

#define SQ 384
#define HDIM 768
#define NHEAD 12
#define DH 64
#define NC 24
#define QKW_I_STRIDE (NC*HDIM)   // 18432
#define OUT_I_STRIDE (NC*SQ)     // 9216

// ---------------- scratch (device globals; no allocation allowed) ----------
__device__ float g_Q[NHEAD*SQ*DH];
__device__ float g_K[NHEAD*SQ*DH];
__device__ float g_V[NHEAD*SQ*DH];
__device__ float g_VT[NHEAD*DH*SQ];      // [h][d][j]  (V transposed, bias added)
__device__ float g_kb[NHEAD*SQ];
__device__ float g_WThi[3*HDIM*HDIM];    // [z][n][k] tf32-hi of W_z^T
__device__ float g_WTlo[3*HDIM*HDIM];    // [z][n][k] tf32-lo residual
__device__ float g_qkW[SQ*NC*HDIM];      // [i][c][e]
__device__ float g_OUT[SQ*NC*SQ];        // [i][c][j]
__device__ float g_C2C[NHEAD*SQ*SQ];     // [h][i][j]
__device__ float g_P[NHEAD*SQ*SQ];       // probs

__device__ __forceinline__ void mma_tf32(float* d, unsigned a0, unsigned a1,
                                         unsigned a2, unsigned a3,
                                         unsigned b0, unsigned b1) {
    asm volatile(
        "mma.sync.aligned.m16n8k8.row.col.f32.tf32.tf32.f32 "
        "{%0,%1,%2,%3}, {%4,%5,%6,%7}, {%8,%9}, {%0,%1,%2,%3};"
        : "+f"(d[0]), "+f"(d[1]), "+f"(d[2]), "+f"(d[3])
        : "r"(a0), "r"(a1), "r"(a2), "r"(a3), "r"(b0), "r"(b1));
}

// split fp32 into tf32 hi + tf32 lo (3xTF32 error compensation)
__device__ __forceinline__ void split_tf32(float x, unsigned& hi, unsigned& lo) {
    unsigned h;
    asm("cvt.rna.tf32.f32 %0, %1;" : "=r"(h) : "f"(x));
    float r = x - __uint_as_float(h);
    unsigned l;
    asm("cvt.rna.tf32.f32 %0, %1;" : "=r"(l) : "f"(r));
    hi = h; lo = l;
}

__device__ __forceinline__ void cp16(void* dst_smem, const void* src_gmem) {
    unsigned d = (unsigned)__cvta_generic_to_shared(dst_smem);
    asm volatile("cp.async.ca.shared.global [%0], [%1], 16;" :: "r"(d), "l"(src_gmem));
}
__device__ __forceinline__ void cp_commit() {
    asm volatile("cp.async.commit_group;");
}
template <int N>
__device__ __forceinline__ void cp_wait() {
    asm volatile("cp.async.wait_group %0;" :: "n"(N));
}

// ================= KT: transpose + PRE-SPLIT W_z -> g_WThi/g_WTlo =========
// One launch per z (fills ncu skip slots; k1 lands 4th).
__global__ void kT_transpose(const float* __restrict__ W, int z)
{
    __shared__ float t[32][33];
    float* WThi = g_WThi + (size_t)z*HDIM*HDIM;
    float* WTlo = g_WTlo + (size_t)z*HDIM*HDIM;
    int n0 = blockIdx.x*32, k0 = blockIdx.y*32;
    int tx = threadIdx.x & 31, ty = threadIdx.x >> 5;   // 256 thr: ty 0..7
    #pragma unroll
    for (int r = 0; r < 32; r += 8)
        t[ty+r][tx] = W[(size_t)(k0+ty+r)*HDIM + n0 + tx];
    __syncthreads();
    #pragma unroll
    for (int r = 0; r < 32; r += 8) {
        float v = t[tx][ty+r];
        unsigned hi, lo;
        split_tf32(v, hi, lo);
        WThi[(size_t)(n0+ty+r)*HDIM + k0 + tx] = __uint_as_float(hi);
        WTlo[(size_t)(n0+ty+r)*HDIM + k0 + tx] = __uint_as_float(lo);
    }
}

// ================= K1: QKV projections, pre-split B, 3-substage pipeline ==
// CTA (h, ib, z): out[i0..63][h*64 + 0..63] = hidden @ W + b
// Sub-stage = 16 k. SM carve per stage s: A = s*3840, Bhi = +1280, Blo = +2560.
#define K1AP 20
#define K1SST 1280            // 64 rows * pitch 20
#define K1NSG 48              // 768 / 16

__global__ void __launch_bounds__(256, 2) k1_qkv(const float* __restrict__ hidden,
                       const float* __restrict__ bq,
                       const float* __restrict__ bk,
                       const float* __restrict__ bv)
{
    __shared__ float SM[3*3*K1SST];   // 45 KB (epilogue reuses first 4352 fl)
    int h = blockIdx.x, ib = blockIdx.y, z = blockIdx.z;
    const float* b = (z==0) ? bq : (z==1) ? bk : bv;
    float* outp    = (z==0) ? g_Q : (z==1) ? g_K : g_V;
    int i0 = ib * 64;
    int tid = threadIdx.x, warp = tid >> 5, lane = tid & 31;
    int gid = lane >> 2, tig = lane & 3;
    int wy = warp & 3;        // i-tile (16 rows)
    int wx = warp >> 2;       // n-half (32 cols)
    int m  = wy * 16;

    const float* abase  = hidden + (size_t)i0*HDIM;
    const float* bhbase = g_WThi + (size_t)z*HDIM*HDIM + (size_t)(h*64)*HDIM;
    const float* blbase = g_WTlo + (size_t)z*HDIM*HDIM + (size_t)(h*64)*HDIM;

    float acc[4][4];
    #pragma unroll
    for (int nt = 0; nt < 4; ++nt)
        #pragma unroll
        for (int r = 0; r < 4; ++r) acc[nt][r] = 0.f;

    // one sub-stage = 16 k: 256 cp16 each for A / Bhi / Blo (1 per thread)
    auto issue = [&](int sg) {
        int s = sg % 3;
        int e0 = sg * 16;
        float* as = SM + s*3840;
        float* bh = as + K1SST;
        float* bl = as + 2*K1SST;
        int r = tid >> 2, q = tid & 3;
        size_t off = (size_t)r*HDIM + e0 + q*4;
        cp16(as + r*K1AP + q*4, abase  + off);
        cp16(bh + r*K1AP + q*4, bhbase + off);
        cp16(bl + r*K1AP + q*4, blbase + off);
    };

    issue(0); cp_commit();
    issue(1); cp_commit();

    for (int sg = 0; sg < K1NSG; ++sg) {
        if (sg < K1NSG-1) cp_wait<1>();   // pending {sg, sg+1} -> completes sg
        else              cp_wait<0>();
        __syncthreads();                  // stage sg%3 visible; (sg-1)%3 free
        if (sg + 2 < K1NSG) { issue(sg + 2); cp_commit(); }

        const float* a  = SM + (sg % 3)*3840;
        const float* bh = a + K1SST;
        const float* bl = a + 2*K1SST;
        #pragma unroll
        for (int ks = 0; ks < 2; ++ks) {
            int eo = ks * 8;
            unsigned ah[4], al[4];
            split_tf32(a[(m+gid  )*K1AP + eo + tig    ], ah[0], al[0]);
            split_tf32(a[(m+gid+8)*K1AP + eo + tig    ], ah[1], al[1]);
            split_tf32(a[(m+gid  )*K1AP + eo + tig + 4], ah[2], al[2]);
            split_tf32(a[(m+gid+8)*K1AP + eo + tig + 4], ah[3], al[3]);
            #pragma unroll
            for (int nt = 0; nt < 4; ++nt) {
                int n = wx*32 + nt*8;
                unsigned bh0 = __float_as_uint(bh[(n+gid)*K1AP + eo + tig    ]);
                unsigned bh1 = __float_as_uint(bh[(n+gid)*K1AP + eo + tig + 4]);
                unsigned bl0 = __float_as_uint(bl[(n+gid)*K1AP + eo + tig    ]);
                unsigned bl1 = __float_as_uint(bl[(n+gid)*K1AP + eo + tig + 4]);
                mma_tf32(acc[nt], ah[0],ah[1],ah[2],ah[3], bh0, bh1);
                mma_tf32(acc[nt], ah[0],ah[1],ah[2],ah[3], bl0, bl1);
                mma_tf32(acc[nt], al[0],al[1],al[2],al[3], bh0, bh1);
            }
        }
    }
    __syncthreads();

    // epilogue: stage [i][n] (pitch 68, reuse SM), add bias, coalesced STG
    #pragma unroll
    for (int nt = 0; nt < 4; ++nt) {
        int r0 = wy*16 + gid, r1 = r0 + 8;
        int nc = wx*32 + nt*8 + tig*2;
        SM[r0*68 + nc    ] = acc[nt][0];
        SM[r0*68 + nc + 1] = acc[nt][1];
        SM[r1*68 + nc    ] = acc[nt][2];
        SM[r1*68 + nc + 1] = acc[nt][3];
    }
    __syncthreads();
    #pragma unroll
    for (int p = 0; p < 4; ++p) {
        int idx = tid + p*256;
        int row = idx >> 4, q = idx & 15;
        float4 v  = *(const float4*)&SM[row*68 + q*4];
        float4 bb = *(const float4*)&b[h*64 + q*4];
        v.x += bb.x; v.y += bb.y; v.z += bb.z; v.w += bb.w;
        *(float4*)(outp + (size_t)(h*SQ + i0 + row)*DH + q*4) = v;
    }
    // extra: V transposed (bias included) for k5's MMA B-operand
    if (z == 2) {
        #pragma unroll
        for (int p = 0; p < 16; ++p) {
            int idx = tid + p*256;          // 4096 = 64n * 64i
            int n = idx >> 6, ii = idx & 63;
            g_VT[(size_t)(h*64 + n)*SQ + i0 + ii] = SM[ii*68 + n] + b[h*64 + n];
        }
    }
}

// ================= K1b: kb[h][j] = k[h,j,:].bpq_h =========================
__global__ void k1b_kb(const float* __restrict__ bpq)
{
    int h = blockIdx.x, j = threadIdx.x;
    const float* kp = g_K + (h*SQ + j)*DH;
    const float* bp = bpq + h*64;
    float s = 0.f;
    #pragma unroll 8
    for (int d = 0; d < DH; ++d) s += kp[d]*bp[d];
    g_kb[h*SQ + j] = s;
}

// ================= K2: qkW[i][c][e], 3xTF32, single-split + middle grid ===
#define K2P 68    // smem pitch; 68 mod 32 == 4 -> conflict-free fragments
__global__ void __launch_bounds__(256) k2_qkw(const float* __restrict__ Wpk,
                                              const float* __restrict__ Wpq)
{
    __shared__ float Asr[64*K2P];   // raw A [i][d]      17.4 KB
    __shared__ float Bhi[32*K2P];   // B hi  [e][d]       8.7 KB
    __shared__ float Blo[32*K2P];   // B lo  [e][d]       8.7 KB
    int ib  = blockIdx.x;           // 0..5
    int c   = blockIdx.y;           // 0..23
    int ebg = blockIdx.z;           // 0..5 (4 eb-tiles each)
    int h  = (c < 12) ? c : c - 12;
    const float* Asrc = (c < 12) ? g_Q : g_K;
    const float* Wp   = (c < 12) ? Wpk : Wpq;
    int i0 = ib * 64;
    int tid = threadIdx.x, warp = tid >> 5, lane = tid & 31;
    int gid = lane >> 2, tig = lane & 3;
    int wy = warp & 3;              // 4 i-tiles of 16 rows
    int wx = warp >> 2;             // 2 e-halves of 16 cols
    int m  = wy * 16;

    #pragma unroll
    for (int p = 0; p < 4; ++p) {
        int idx = tid + p*256;
        int row = idx >> 4, q = idx & 15;
        *(float4*)&Asr[row*K2P + q*4] =
            *(const float4*)(Asrc + (size_t)(h*SQ + i0 + row)*DH + q*4);
    }
    __syncthreads();

    unsigned ah[8][4], al[8][4];
    #pragma unroll
    for (int ks = 0; ks < 8; ++ks) {
        int eo = ks * 8;
        split_tf32(Asr[(m+gid  )*K2P + eo + tig    ], ah[ks][0], al[ks][0]);
        split_tf32(Asr[(m+gid+8)*K2P + eo + tig    ], ah[ks][1], al[ks][1]);
        split_tf32(Asr[(m+gid  )*K2P + eo + tig + 4], ah[ks][2], al[ks][2]);
        split_tf32(Asr[(m+gid+8)*K2P + eo + tig + 4], ah[ks][3], al[ks][3]);
    }

    float4 rb[2];
    auto loadB = [&](int e0) {
        #pragma unroll
        for (int p = 0; p < 2; ++p) {
            int idx = tid + p*256;
            int row = idx >> 4, q = idx & 15;
            rb[p] = *(const float4*)(Wp + (size_t)(e0 + row)*HDIM + h*64 + q*4);
        }
    };
    int eb0 = ebg * 4;
    loadB(eb0 * 32);

    for (int t = 0; t < 4; ++t) {
        int eb = eb0 + t;
        #pragma unroll
        for (int p = 0; p < 2; ++p) {
            int idx = tid + p*256;
            int row = idx >> 4, q = idx & 15;
            float4 v = rb[p];
            unsigned h0,l0,h1,l1,h2,l2,h3,l3;
            split_tf32(v.x, h0, l0); split_tf32(v.y, h1, l1);
            split_tf32(v.z, h2, l2); split_tf32(v.w, h3, l3);
            float4 hv = make_float4(__uint_as_float(h0), __uint_as_float(h1),
                                    __uint_as_float(h2), __uint_as_float(h3));
            float4 lv = make_float4(__uint_as_float(l0), __uint_as_float(l1),
                                    __uint_as_float(l2), __uint_as_float(l3));
            *(float4*)&Bhi[row*K2P + q*4] = hv;
            *(float4*)&Blo[row*K2P + q*4] = lv;
        }
        if (t + 1 < 4) loadB((eb + 1) * 32);
        __syncthreads();

        float acc[2][4];
        #pragma unroll
        for (int nt = 0; nt < 2; ++nt)
            #pragma unroll
            for (int r = 0; r < 4; ++r) acc[nt][r] = 0.f;

        #pragma unroll
        for (int ks = 0; ks < 8; ++ks) {
            int eo = ks * 8;
            #pragma unroll
            for (int nt = 0; nt < 2; ++nt) {
                int n = wx*16 + nt*8;
                unsigned bh0 = __float_as_uint(Bhi[(n+gid)*K2P + eo + tig    ]);
                unsigned bh1 = __float_as_uint(Bhi[(n+gid)*K2P + eo + tig + 4]);
                unsigned bl0 = __float_as_uint(Blo[(n+gid)*K2P + eo + tig    ]);
                unsigned bl1 = __float_as_uint(Blo[(n+gid)*K2P + eo + tig + 4]);
                mma_tf32(acc[nt], ah[ks][0],ah[ks][1],ah[ks][2],ah[ks][3], bh0, bh1);
                mma_tf32(acc[nt], ah[ks][0],ah[ks][1],ah[ks][2],ah[ks][3], bl0, bl1);
                mma_tf32(acc[nt], al[ks][0],al[ks][1],al[ks][2],al[ks][3], bh0, bh1);
            }
        }

        int e0 = eb * 32;
        #pragma unroll
        for (int nt = 0; nt < 2; ++nt) {
            int n = wx*16 + nt*8;
            float* o0 = g_qkW + (size_t)(i0 + m + gid    )*QKW_I_STRIDE + c*HDIM + e0 + n + tig*2;
            float* o1 = g_qkW + (size_t)(i0 + m + gid + 8)*QKW_I_STRIDE + c*HDIM + e0 + n + tig*2;
            *(float2*)o0 = make_float2(acc[nt][0], acc[nt][1]);
            *(float2*)o1 = make_float2(acc[nt][2], acc[nt][3]);
        }
        __syncthreads();
    }
}

// ================= K2b: c2c[h][i][j], 3xTF32 MMA ==========================
__global__ void __launch_bounds__(256) k2b_c2c()
{
    __shared__ float As2[64*K2P];
    __shared__ float Bs2[64*K2P];
    int jb = blockIdx.x, ib = blockIdx.y, h = blockIdx.z;
    int i0 = ib*64, j0 = jb*64;
    int tid = threadIdx.x, warp = tid >> 5, lane = tid & 31;
    int gid = lane >> 2, tig = lane & 3;
    int wy = warp & 3, wx = warp >> 2;

    #pragma unroll
    for (int p = 0; p < 4; ++p) {
        int idx = tid + p*256;
        int row = idx >> 4, q = idx & 15;
        *(float4*)&As2[row*K2P + q*4] = *(const float4*)(g_Q + (size_t)(h*SQ + i0 + row)*DH + q*4);
        *(float4*)&Bs2[row*K2P + q*4] = *(const float4*)(g_K + (size_t)(h*SQ + j0 + row)*DH + q*4);
    }
    __syncthreads();

    float acc[4][4];
    #pragma unroll
    for (int nt = 0; nt < 4; ++nt)
        #pragma unroll
        for (int r = 0; r < 4; ++r) acc[nt][r] = 0.f;

    #pragma unroll
    for (int ks = 0; ks < 8; ++ks) {
        int eo = ks * 8;
        int m = wy * 16;
        unsigned ah[4], al[4];
        split_tf32(As2[(m+gid  )*K2P + eo + tig    ], ah[0], al[0]);
        split_tf32(As2[(m+gid+8)*K2P + eo + tig    ], ah[1], al[1]);
        split_tf32(As2[(m+gid  )*K2P + eo + tig + 4], ah[2], al[2]);
        split_tf32(As2[(m+gid+8)*K2P + eo + tig + 4], ah[3], al[3]);
        #pragma unroll
        for (int nt = 0; nt < 4; ++nt) {
            int n = wx*32 + nt*8;
            unsigned bh0, bl0, bh1, bl1;
            split_tf32(Bs2[(n+gid)*K2P + eo + tig    ], bh0, bl0);
            split_tf32(Bs2[(n+gid)*K2P + eo + tig + 4], bh1, bl1);
            mma_tf32(acc[nt], ah[0],ah[1],ah[2],ah[3], bh0, bh1);
            mma_tf32(acc[nt], ah[0],ah[1],ah[2],ah[3], bl0, bl1);
            mma_tf32(acc[nt], al[0],al[1],al[2],al[3], bh0, bh1);
        }
    }
    __syncthreads();

    #pragma unroll
    for (int nt = 0; nt < 4; ++nt) {
        int r0 = wy*16 + gid, r1 = r0 + 8;
        int nc = wx*32 + nt*8 + tig*2;
        As2[r0*K2P + nc    ] = acc[nt][0];
        As2[r0*K2P + nc + 1] = acc[nt][1];
        As2[r1*K2P + nc    ] = acc[nt][2];
        As2[r1*K2P + nc + 1] = acc[nt][3];
    }
    __syncthreads();
    #pragma unroll
    for (int p = 0; p < 4; ++p) {
        int idx = tid + p*256;
        int row = idx >> 4, q = idx & 15;
        float4 v = *(const float4*)&As2[row*K2P + q*4];
        *(float4*)(g_C2C + ((size_t)h*SQ + i0 + row)*SQ + j0 + q*4) = v;
    }
}

// ================= K3: pos contraction, tf32 MMA, pair-issue cp.async =====
#define JW3 128                   // j rows per CTA
#define AP3 20                    // smem pitch (floats)
#define ASTG (JW3*AP3)            // 2560 floats per stage
#define BSTG (NC*AP3)             // 480 floats per stage
#define NG3  24                   // issue groups (2 chunks each)
#define EP3 132                   // epilogue [c][j] pitch

__global__ void __launch_bounds__(256, 4) k3_pos(const float* __restrict__ pos)
{
    __shared__ float As[4*ASTG];   // 40 KB
    __shared__ float Bs[4*BSTG];   // 7.5 KB
    int jb = blockIdx.x;           // 0..2
    int i  = blockIdx.y;           // 0..383
    int tid = threadIdx.x;         // 256 = 8 warps
    int warp = tid >> 5, lane = tid & 31;
    int gid = lane >> 2, tig = lane & 3;
    int j0w = warp * 16;

    const float* posi = pos + (size_t)i * (SQ*HDIM) + (size_t)jb * JW3 * HDIM;
    const float* wsrc = g_qkW + (size_t)i * QKW_I_STRIDE;

    float acc[3][4];
    #pragma unroll
    for (int ct = 0; ct < 3; ++ct)
        #pragma unroll
        for (int r = 0; r < 4; ++r) acc[ct][r] = 0.f;

    auto issuePair = [&](int k) {
        int e0 = k * 32;
        int sA = (2*k) & 3;
        float* asb = As + sA*ASTG;
        float* bsb = Bs + sA*BSTG;
        #pragma unroll
        for (int p = 0; p < 4; ++p) {
            int idx = tid + p*256;
            int j = idx >> 3, q = idx & 7;
            cp16(asb + (q>>2)*ASTG + j*AP3 + (q&3)*4,
                 posi + (size_t)j*HDIM + e0 + q*4);
        }
        if (tid < 192) {
            int c = tid >> 3, q = tid & 7;
            cp16(bsb + (q>>2)*BSTG + c*AP3 + (q&3)*4,
                 wsrc + (size_t)c*HDIM + e0 + q*4);
        }
    };

    issuePair(0); cp_commit();
    issuePair(1); cp_commit();

    for (int k = 0; k < NG3; ++k) {
        if (k < NG3-1) cp_wait<1>();
        else           cp_wait<0>();
        __syncthreads();

        #pragma unroll
        for (int half = 0; half < 2; ++half) {
            int s = (2*k + half) & 3;
            const float* a = As + s*ASTG;
            const float* b = Bs + s*BSTG;
            #pragma unroll
            for (int ks = 0; ks < 2; ++ks) {
                int eo = ks * 8;
                unsigned a0 = __float_as_uint(a[(j0w + gid    )*AP3 + eo + tig    ]);
                unsigned a1 = __float_as_uint(a[(j0w + gid + 8)*AP3 + eo + tig    ]);
                unsigned a2 = __float_as_uint(a[(j0w + gid    )*AP3 + eo + tig + 4]);
                unsigned a3 = __float_as_uint(a[(j0w + gid + 8)*AP3 + eo + tig + 4]);
                #pragma unroll
                for (int ct = 0; ct < 3; ++ct) {
                    unsigned b0 = __float_as_uint(b[(ct*8 + gid)*AP3 + eo + tig    ]);
                    unsigned b1 = __float_as_uint(b[(ct*8 + gid)*AP3 + eo + tig + 4]);
                    mma_tf32(acc[ct], a0, a1, a2, a3, b0, b1);
                }
            }
        }
        __syncthreads();
        if (k + 2 < NG3) { issuePair(k + 2); cp_commit(); }
    }

    #pragma unroll
    for (int ct = 0; ct < 3; ++ct) {
        int c = ct*8 + tig*2;
        As[ c   *EP3 + j0w + gid    ] = acc[ct][0];
        As[(c+1)*EP3 + j0w + gid    ] = acc[ct][1];
        As[ c   *EP3 + j0w + gid + 8] = acc[ct][2];
        As[(c+1)*EP3 + j0w + gid + 8] = acc[ct][3];
    }
    __syncthreads();
    float* o_base = g_OUT + (size_t)i * OUT_I_STRIDE + jb*JW3;
    #pragma unroll
    for (int p = 0; p < 3; ++p) {
        int idx = tid + p*256;
        int c = idx >> 5, j4 = (idx & 31) * 4;
        float4 v = *(const float4*)&As[c*EP3 + j4];
        *(float4*)(o_base + c*SQ + j4) = v;
    }
}

// ================= KS: fused scores assembly + softmax ====================
#define SPITCH 386
__global__ void __launch_bounds__(256) ks_fused(const float* __restrict__ mask)
{
    __shared__ float S[16*SPITCH];        // 24.7KB
    int ib = blockIdx.x, h = blockIdx.y;
    int i0 = ib * 16;
    int tid = threadIdx.x;

    #pragma unroll
    for (int p = 0; p < 24; ++p) {
        int idx = tid + p*256;
        int ii = idx / 384, j = idx % 384;
        float v = g_C2C[((size_t)h*SQ + i0 + ii)*SQ + j]
                + g_OUT[(size_t)(i0 + ii)*OUT_I_STRIDE + h*SQ + j]
                + g_kb[h*SQ + j];
        S[ii*SPITCH + j] = v * 0.125f + mask[j];
    }
    __syncthreads();

    {
        int ti = tid & 15, tj = tid >> 4;
        #pragma unroll
        for (int t = 0; t < 24; ++t) {
            int j = t*16 + tj;
            float v = g_OUT[(size_t)j*OUT_I_STRIDE + (12 + h)*SQ + i0 + ti];
            S[ti*SPITCH + j] += v * 0.125f;
        }
    }
    __syncthreads();

    int warp = tid >> 5, lane = tid & 31;
    #pragma unroll
    for (int w2 = 0; w2 < 2; ++w2) {
        int il = warp*2 + w2;
        const float* srow = &S[il*SPITCH];
        float x[12];
        float m = -1e30f;
        #pragma unroll
        for (int t = 0; t < 12; ++t) { x[t] = srow[lane + t*32]; m = fmaxf(m, x[t]); }
        #pragma unroll
        for (int o = 16; o; o >>= 1) m = fmaxf(m, __shfl_xor_sync(0xffffffffu, m, o));
        float ss = 0.f;
        #pragma unroll
        for (int t = 0; t < 12; ++t) { x[t] = __expf(x[t] - m); ss += x[t]; }
        #pragma unroll
        for (int o = 16; o; o >>= 1) ss += __shfl_xor_sync(0xffffffffu, ss, o);
        float inv = 1.f / ss;
        float* prow = g_P + ((size_t)h*SQ + i0 + il)*SQ;
        #pragma unroll
        for (int t = 0; t < 12; ++t) prow[lane + t*32] = x[t] * inv;
    }
}

// ================= K5: context = P @ V^T via 3xTF32 MMA ===================
#define K5P 68
__global__ void __launch_bounds__(256) k5_pv(float* __restrict__ out)
{
    __shared__ float As5[32*K5P];   // [i][k]  8.7 KB
    __shared__ float Bs5[64*K5P];   // [n][k] 17.4 KB
    int ib = blockIdx.x, h = blockIdx.y;
    int i0 = ib * 32;
    int tid = threadIdx.x, warp = tid >> 5, lane = tid & 31;
    int gid = lane >> 2, tig = lane & 3;
    int wy = warp & 1;         // i-tile (16 rows)
    int wx = warp >> 1;        // n-block (16 cols), nt in {0,1}

    float acc[2][4];
    #pragma unroll
    for (int nt = 0; nt < 2; ++nt)
        #pragma unroll
        for (int r = 0; r < 4; ++r) acc[nt][r] = 0.f;

    for (int kc = 0; kc < 6; ++kc) {
        int k0 = kc * 64;
        __syncthreads();
        #pragma unroll
        for (int p = 0; p < 2; ++p) {
            int idx = tid + p*256;
            int row = idx >> 4, q = idx & 15;
            *(float4*)&As5[row*K5P + q*4] =
                *(const float4*)(g_P + ((size_t)h*SQ + i0 + row)*SQ + k0 + q*4);
        }
        #pragma unroll
        for (int p = 0; p < 4; ++p) {
            int idx = tid + p*256;
            int row = idx >> 4, q = idx & 15;
            *(float4*)&Bs5[row*K5P + q*4] =
                *(const float4*)(g_VT + ((size_t)h*64 + row)*SQ + k0 + q*4);
        }
        __syncthreads();

        #pragma unroll
        for (int ks = 0; ks < 8; ++ks) {
            int eo = ks * 8;
            int m = wy * 16;
            unsigned ah[4], al[4];
            split_tf32(As5[(m+gid  )*K5P + eo + tig    ], ah[0], al[0]);
            split_tf32(As5[(m+gid+8)*K5P + eo + tig    ], ah[1], al[1]);
            split_tf32(As5[(m+gid  )*K5P + eo + tig + 4], ah[2], al[2]);
            split_tf32(As5[(m+gid+8)*K5P + eo + tig + 4], ah[3], al[3]);
            #pragma unroll
            for (int nt = 0; nt < 2; ++nt) {
                int n = wx*16 + nt*8;
                unsigned bh0, bl0, bh1, bl1;
                split_tf32(Bs5[(n+gid)*K5P + eo + tig    ], bh0, bl0);
                split_tf32(Bs5[(n+gid)*K5P + eo + tig + 4], bh1, bl1);
                mma_tf32(acc[nt], ah[0],ah[1],ah[2],ah[3], bh0, bh1);
                mma_tf32(acc[nt], ah[0],ah[1],ah[2],ah[3], bl0, bl1);
                mma_tf32(acc[nt], al[0],al[1],al[2],al[3], bh0, bh1);
            }
        }
    }
    __syncthreads();

    #pragma unroll
    for (int nt = 0; nt < 2; ++nt) {
        int r0 = wy*16 + gid, r1 = r0 + 8;
        int nc = wx*16 + nt*8 + tig*2;
        As5[r0*K5P + nc    ] = acc[nt][0];
        As5[r0*K5P + nc + 1] = acc[nt][1];
        As5[r1*K5P + nc    ] = acc[nt][2];
        As5[r1*K5P + nc + 1] = acc[nt][3];
    }
    __syncthreads();
    #pragma unroll
    for (int p = 0; p < 2; ++p) {
        int idx = tid + p*256;
        int row = idx >> 4, q = idx & 15;
        float4 v = *(const float4*)&As5[row*K5P + q*4];
        *(float4*)(out + (size_t)(i0 + row)*HDIM + h*64 + q*4) = v;
    }
}

// ================= launch =================================================
extern "C" void kernel_launch(void* const* d_in, const int* in_sizes, int n_in,
                              void* d_out, int out_size)
{
    const float* hidden = (const float*)d_in[0];
    const float* mask   = (const float*)d_in[1];
    const float* pos    = (const float*)d_in[2];
    const float* Wq  = (const float*)d_in[3];
    const float* bq  = (const float*)d_in[4];
    const float* Wk  = (const float*)d_in[5];
    const float* bk  = (const float*)d_in[6];
    const float* Wv  = (const float*)d_in[7];
    const float* bv  = (const float*)d_in[8];
    const float* Wpk = (const float*)d_in[9];
    // d_in[10] = bpk: constant over j -> softmax-invariant -> cancels exactly
    const float* Wpq = (const float*)d_in[11];
    const float* bpq = (const float*)d_in[12];
    float* out = (float*)d_out;

    // kT split into 3 launches so k1_qkv lands in the sampled 4th slot.
    kT_transpose<<<dim3(24, 24), 256>>>(Wq, 0);
    kT_transpose<<<dim3(24, 24), 256>>>(Wk, 1);
    kT_transpose<<<dim3(24, 24), 256>>>(Wv, 2);
    k1_qkv<<<dim3(12, 6, 3), 256>>>(hidden, bq, bk, bv);
    k1b_kb<<<12, 384>>>(bpq);
    k2_qkw<<<dim3(6, 24, 6), 256>>>(Wpk, Wpq);
    k3_pos<<<dim3(3, 384), 256>>>(pos);
    k2b_c2c<<<dim3(6, 6, 12), 256>>>();
    ks_fused<<<dim3(24, 12), 256>>>(mask);
    k5_pv<<<dim3(12, 12), 256>>>(out);
}

// round 15
// speedup vs baseline: 1.0027x; 1.0027x over previous
#include <cuda_runtime.h>
#include <math.h>

#define SQ 384
#define HDIM 768
#define NHEAD 12
#define DH 64
#define NC 24
#define QKW_I_STRIDE (NC*HDIM)   // 18432
#define OUT_I_STRIDE (NC*SQ)     // 9216

// ---------------- scratch (device globals; no allocation allowed) ----------
__device__ float g_Q[NHEAD*SQ*DH];
__device__ float g_K[NHEAD*SQ*DH];
__device__ float g_V[NHEAD*SQ*DH];
__device__ float g_VT[NHEAD*DH*SQ];      // [h][d][j]  (V transposed, bias added)
__device__ float g_kb[NHEAD*SQ];
__device__ float g_WThi[3*HDIM*HDIM];    // [z][n][k] tf32-hi of W_z^T
__device__ float g_WTlo[3*HDIM*HDIM];    // [z][n][k] tf32-lo residual
__device__ float g_qkW[SQ*NC*HDIM];      // [i][c][e]
__device__ float g_OUT[SQ*NC*SQ];        // [i][c][j]
__device__ float g_C2C[NHEAD*SQ*SQ];     // [h][i][j]
__device__ float g_P[NHEAD*SQ*SQ];       // probs

__device__ __forceinline__ void mma_tf32(float* d, unsigned a0, unsigned a1,
                                         unsigned a2, unsigned a3,
                                         unsigned b0, unsigned b1) {
    asm volatile(
        "mma.sync.aligned.m16n8k8.row.col.f32.tf32.tf32.f32 "
        "{%0,%1,%2,%3}, {%4,%5,%6,%7}, {%8,%9}, {%0,%1,%2,%3};"
        : "+f"(d[0]), "+f"(d[1]), "+f"(d[2]), "+f"(d[3])
        : "r"(a0), "r"(a1), "r"(a2), "r"(a3), "r"(b0), "r"(b1));
}

// split fp32 into tf32 hi + tf32 lo (3xTF32 error compensation)
__device__ __forceinline__ void split_tf32(float x, unsigned& hi, unsigned& lo) {
    unsigned h;
    asm("cvt.rna.tf32.f32 %0, %1;" : "=r"(h) : "f"(x));
    float r = x - __uint_as_float(h);
    unsigned l;
    asm("cvt.rna.tf32.f32 %0, %1;" : "=r"(l) : "f"(r));
    hi = h; lo = l;
}

__device__ __forceinline__ void cp16(void* dst_smem, const void* src_gmem) {
    unsigned d = (unsigned)__cvta_generic_to_shared(dst_smem);
    asm volatile("cp.async.ca.shared.global [%0], [%1], 16;" :: "r"(d), "l"(src_gmem));
}
__device__ __forceinline__ void cp_commit() {
    asm volatile("cp.async.commit_group;");
}
template <int N>
__device__ __forceinline__ void cp_wait() {
    asm volatile("cp.async.wait_group %0;" :: "n"(N));
}

// ================= KT: transpose + PRE-SPLIT W_z -> g_WThi/g_WTlo =========
__global__ void kT_transpose(const float* __restrict__ W, int z)
{
    __shared__ float t[32][33];
    float* WThi = g_WThi + (size_t)z*HDIM*HDIM;
    float* WTlo = g_WTlo + (size_t)z*HDIM*HDIM;
    int n0 = blockIdx.x*32, k0 = blockIdx.y*32;
    int tx = threadIdx.x & 31, ty = threadIdx.x >> 5;   // 256 thr: ty 0..7
    #pragma unroll
    for (int r = 0; r < 32; r += 8)
        t[ty+r][tx] = W[(size_t)(k0+ty+r)*HDIM + n0 + tx];
    __syncthreads();
    #pragma unroll
    for (int r = 0; r < 32; r += 8) {
        float v = t[tx][ty+r];
        unsigned hi, lo;
        split_tf32(v, hi, lo);
        WThi[(size_t)(n0+ty+r)*HDIM + k0 + tx] = __uint_as_float(hi);
        WTlo[(size_t)(n0+ty+r)*HDIM + k0 + tx] = __uint_as_float(lo);
    }
}

// ================= K1: QKV projections, pre-split B, 32-row i-tiles =======
// CTA (h, ib, z): out[i0..i0+31][h*64 + 0..63] = hidden @ W + b
// Sub-stage = 16 k. Stage layout: A(640) + Bhi(1280) + Blo(1280) = 3200 fl.
#define K1AP 20
#define K1AST 640             // 32 rows * pitch 20
#define K1BST 1280            // 64 rows * pitch 20
#define K1STG (K1AST + 2*K1BST)  // 3200 floats
#define K1NSG 48              // 768 / 16

__global__ void __launch_bounds__(256, 3) k1_qkv(const float* __restrict__ hidden,
                       const float* __restrict__ bq,
                       const float* __restrict__ bk,
                       const float* __restrict__ bv)
{
    __shared__ float SM[3*K1STG];     // 37.5 KB (epilogue reuses 32*68=2176 fl)
    int h = blockIdx.x, ib = blockIdx.y, z = blockIdx.z;
    const float* b = (z==0) ? bq : (z==1) ? bk : bv;
    float* outp    = (z==0) ? g_Q : (z==1) ? g_K : g_V;
    int i0 = ib * 32;
    int tid = threadIdx.x, warp = tid >> 5, lane = tid & 31;
    int gid = lane >> 2, tig = lane & 3;
    int wy = warp & 1;        // i-tile (16 rows)
    int wx = warp >> 1;       // n-quarter (16 cols)
    int m  = wy * 16;

    const float* abase  = hidden + (size_t)i0*HDIM;
    const float* bhbase = g_WThi + (size_t)z*HDIM*HDIM + (size_t)(h*64)*HDIM;
    const float* blbase = g_WTlo + (size_t)z*HDIM*HDIM + (size_t)(h*64)*HDIM;

    float acc[2][4];
    #pragma unroll
    for (int nt = 0; nt < 2; ++nt)
        #pragma unroll
        for (int r = 0; r < 4; ++r) acc[nt][r] = 0.f;

    // one sub-stage = 16 k: B = 256 cp16 x2 (1/thread), A = 128 cp16 (tid<128)
    auto issue = [&](int sg) {
        int s = sg % 3;
        int e0 = sg * 16;
        float* as = SM + s*K1STG;
        float* bh = as + K1AST;
        float* bl = bh + K1BST;
        int r = tid >> 2, q = tid & 3;
        size_t boff = (size_t)r*HDIM + e0 + q*4;
        cp16(bh + r*K1AP + q*4, bhbase + boff);
        cp16(bl + r*K1AP + q*4, blbase + boff);
        if (tid < 128)
            cp16(as + r*K1AP + q*4, abase + boff);
    };

    issue(0); cp_commit();
    issue(1); cp_commit();

    for (int sg = 0; sg < K1NSG; ++sg) {
        if (sg < K1NSG-1) cp_wait<1>();   // pending {sg, sg+1} -> completes sg
        else              cp_wait<0>();
        __syncthreads();                  // stage sg%3 visible; (sg-1)%3 free
        if (sg + 2 < K1NSG) { issue(sg + 2); cp_commit(); }

        const float* a  = SM + (sg % 3)*K1STG;
        const float* bh = a + K1AST;
        const float* bl = bh + K1BST;
        #pragma unroll
        for (int ks = 0; ks < 2; ++ks) {
            int eo = ks * 8;
            unsigned ah[4], al[4];
            split_tf32(a[(m+gid  )*K1AP + eo + tig    ], ah[0], al[0]);
            split_tf32(a[(m+gid+8)*K1AP + eo + tig    ], ah[1], al[1]);
            split_tf32(a[(m+gid  )*K1AP + eo + tig + 4], ah[2], al[2]);
            split_tf32(a[(m+gid+8)*K1AP + eo + tig + 4], ah[3], al[3]);
            #pragma unroll
            for (int nt = 0; nt < 2; ++nt) {
                int n = wx*16 + nt*8;
                unsigned bh0 = __float_as_uint(bh[(n+gid)*K1AP + eo + tig    ]);
                unsigned bh1 = __float_as_uint(bh[(n+gid)*K1AP + eo + tig + 4]);
                unsigned bl0 = __float_as_uint(bl[(n+gid)*K1AP + eo + tig    ]);
                unsigned bl1 = __float_as_uint(bl[(n+gid)*K1AP + eo + tig + 4]);
                mma_tf32(acc[nt], ah[0],ah[1],ah[2],ah[3], bh0, bh1);
                mma_tf32(acc[nt], ah[0],ah[1],ah[2],ah[3], bl0, bl1);
                mma_tf32(acc[nt], al[0],al[1],al[2],al[3], bh0, bh1);
            }
        }
    }
    __syncthreads();

    // epilogue: stage [i 0..31][n 0..63] (pitch 68), add bias, coalesced STG
    #pragma unroll
    for (int nt = 0; nt < 2; ++nt) {
        int r0 = wy*16 + gid, r1 = r0 + 8;
        int nc = wx*16 + nt*8 + tig*2;
        SM[r0*68 + nc    ] = acc[nt][0];
        SM[r0*68 + nc + 1] = acc[nt][1];
        SM[r1*68 + nc    ] = acc[nt][2];
        SM[r1*68 + nc + 1] = acc[nt][3];
    }
    __syncthreads();
    #pragma unroll
    for (int p = 0; p < 2; ++p) {
        int idx = tid + p*256;              // 32 rows x 16 float4 = 512
        int row = idx >> 4, q = idx & 15;
        float4 v  = *(const float4*)&SM[row*68 + q*4];
        float4 bb = *(const float4*)&b[h*64 + q*4];
        v.x += bb.x; v.y += bb.y; v.z += bb.z; v.w += bb.w;
        *(float4*)(outp + (size_t)(h*SQ + i0 + row)*DH + q*4) = v;
    }
    // extra: V transposed (bias included) for k5's MMA B-operand
    if (z == 2) {
        #pragma unroll
        for (int p = 0; p < 8; ++p) {
            int idx = tid + p*256;          // 2048 = 64n * 32i
            int n = idx >> 5, ii = idx & 31;
            g_VT[(size_t)(h*64 + n)*SQ + i0 + ii] = SM[ii*68 + n] + b[h*64 + n];
        }
    }
}

// ================= K1b: kb[h][j] = k[h,j,:].bpq_h =========================
__global__ void k1b_kb(const float* __restrict__ bpq)
{
    int h = blockIdx.x, j = threadIdx.x;
    const float* kp = g_K + (h*SQ + j)*DH;
    const float* bp = bpq + h*64;
    float s = 0.f;
    #pragma unroll 8
    for (int d = 0; d < DH; ++d) s += kp[d]*bp[d];
    g_kb[h*SQ + j] = s;
}

// ================= K2: qkW[i][c][e], 3xTF32, single-split + middle grid ===
#define K2P 68    // smem pitch; 68 mod 32 == 4 -> conflict-free fragments
__global__ void __launch_bounds__(256) k2_qkw(const float* __restrict__ Wpk,
                                              const float* __restrict__ Wpq)
{
    __shared__ float Asr[64*K2P];   // raw A [i][d]      17.4 KB
    __shared__ float Bhi[32*K2P];   // B hi  [e][d]       8.7 KB
    __shared__ float Blo[32*K2P];   // B lo  [e][d]       8.7 KB
    int ib  = blockIdx.x;           // 0..5
    int c   = blockIdx.y;           // 0..23
    int ebg = blockIdx.z;           // 0..5 (4 eb-tiles each)
    int h  = (c < 12) ? c : c - 12;
    const float* Asrc = (c < 12) ? g_Q : g_K;
    const float* Wp   = (c < 12) ? Wpk : Wpq;
    int i0 = ib * 64;
    int tid = threadIdx.x, warp = tid >> 5, lane = tid & 31;
    int gid = lane >> 2, tig = lane & 3;
    int wy = warp & 3;              // 4 i-tiles of 16 rows
    int wx = warp >> 2;             // 2 e-halves of 16 cols
    int m  = wy * 16;

    #pragma unroll
    for (int p = 0; p < 4; ++p) {
        int idx = tid + p*256;
        int row = idx >> 4, q = idx & 15;
        *(float4*)&Asr[row*K2P + q*4] =
            *(const float4*)(Asrc + (size_t)(h*SQ + i0 + row)*DH + q*4);
    }
    __syncthreads();

    unsigned ah[8][4], al[8][4];
    #pragma unroll
    for (int ks = 0; ks < 8; ++ks) {
        int eo = ks * 8;
        split_tf32(Asr[(m+gid  )*K2P + eo + tig    ], ah[ks][0], al[ks][0]);
        split_tf32(Asr[(m+gid+8)*K2P + eo + tig    ], ah[ks][1], al[ks][1]);
        split_tf32(Asr[(m+gid  )*K2P + eo + tig + 4], ah[ks][2], al[ks][2]);
        split_tf32(Asr[(m+gid+8)*K2P + eo + tig + 4], ah[ks][3], al[ks][3]);
    }

    float4 rb[2];
    auto loadB = [&](int e0) {
        #pragma unroll
        for (int p = 0; p < 2; ++p) {
            int idx = tid + p*256;
            int row = idx >> 4, q = idx & 15;
            rb[p] = *(const float4*)(Wp + (size_t)(e0 + row)*HDIM + h*64 + q*4);
        }
    };
    int eb0 = ebg * 4;
    loadB(eb0 * 32);

    for (int t = 0; t < 4; ++t) {
        int eb = eb0 + t;
        #pragma unroll
        for (int p = 0; p < 2; ++p) {
            int idx = tid + p*256;
            int row = idx >> 4, q = idx & 15;
            float4 v = rb[p];
            unsigned h0,l0,h1,l1,h2,l2,h3,l3;
            split_tf32(v.x, h0, l0); split_tf32(v.y, h1, l1);
            split_tf32(v.z, h2, l2); split_tf32(v.w, h3, l3);
            float4 hv = make_float4(__uint_as_float(h0), __uint_as_float(h1),
                                    __uint_as_float(h2), __uint_as_float(h3));
            float4 lv = make_float4(__uint_as_float(l0), __uint_as_float(l1),
                                    __uint_as_float(l2), __uint_as_float(l3));
            *(float4*)&Bhi[row*K2P + q*4] = hv;
            *(float4*)&Blo[row*K2P + q*4] = lv;
        }
        if (t + 1 < 4) loadB((eb + 1) * 32);
        __syncthreads();

        float acc[2][4];
        #pragma unroll
        for (int nt = 0; nt < 2; ++nt)
            #pragma unroll
            for (int r = 0; r < 4; ++r) acc[nt][r] = 0.f;

        #pragma unroll
        for (int ks = 0; ks < 8; ++ks) {
            int eo = ks * 8;
            #pragma unroll
            for (int nt = 0; nt < 2; ++nt) {
                int n = wx*16 + nt*8;
                unsigned bh0 = __float_as_uint(Bhi[(n+gid)*K2P + eo + tig    ]);
                unsigned bh1 = __float_as_uint(Bhi[(n+gid)*K2P + eo + tig + 4]);
                unsigned bl0 = __float_as_uint(Blo[(n+gid)*K2P + eo + tig    ]);
                unsigned bl1 = __float_as_uint(Blo[(n+gid)*K2P + eo + tig + 4]);
                mma_tf32(acc[nt], ah[ks][0],ah[ks][1],ah[ks][2],ah[ks][3], bh0, bh1);
                mma_tf32(acc[nt], ah[ks][0],ah[ks][1],ah[ks][2],ah[ks][3], bl0, bl1);
                mma_tf32(acc[nt], al[ks][0],al[ks][1],al[ks][2],al[ks][3], bh0, bh1);
            }
        }

        int e0 = eb * 32;
        #pragma unroll
        for (int nt = 0; nt < 2; ++nt) {
            int n = wx*16 + nt*8;
            float* o0 = g_qkW + (size_t)(i0 + m + gid    )*QKW_I_STRIDE + c*HDIM + e0 + n + tig*2;
            float* o1 = g_qkW + (size_t)(i0 + m + gid + 8)*QKW_I_STRIDE + c*HDIM + e0 + n + tig*2;
            *(float2*)o0 = make_float2(acc[nt][0], acc[nt][1]);
            *(float2*)o1 = make_float2(acc[nt][2], acc[nt][3]);
        }
        __syncthreads();
    }
}

// ================= K2b: c2c[h][i][j], 3xTF32 MMA ==========================
__global__ void __launch_bounds__(256) k2b_c2c()
{
    __shared__ float As2[64*K2P];
    __shared__ float Bs2[64*K2P];
    int jb = blockIdx.x, ib = blockIdx.y, h = blockIdx.z;
    int i0 = ib*64, j0 = jb*64;
    int tid = threadIdx.x, warp = tid >> 5, lane = tid & 31;
    int gid = lane >> 2, tig = lane & 3;
    int wy = warp & 3, wx = warp >> 2;

    #pragma unroll
    for (int p = 0; p < 4; ++p) {
        int idx = tid + p*256;
        int row = idx >> 4, q = idx & 15;
        *(float4*)&As2[row*K2P + q*4] = *(const float4*)(g_Q + (size_t)(h*SQ + i0 + row)*DH + q*4);
        *(float4*)&Bs2[row*K2P + q*4] = *(const float4*)(g_K + (size_t)(h*SQ + j0 + row)*DH + q*4);
    }
    __syncthreads();

    float acc[4][4];
    #pragma unroll
    for (int nt = 0; nt < 4; ++nt)
        #pragma unroll
        for (int r = 0; r < 4; ++r) acc[nt][r] = 0.f;

    #pragma unroll
    for (int ks = 0; ks < 8; ++ks) {
        int eo = ks * 8;
        int m = wy * 16;
        unsigned ah[4], al[4];
        split_tf32(As2[(m+gid  )*K2P + eo + tig    ], ah[0], al[0]);
        split_tf32(As2[(m+gid+8)*K2P + eo + tig    ], ah[1], al[1]);
        split_tf32(As2[(m+gid  )*K2P + eo + tig + 4], ah[2], al[2]);
        split_tf32(As2[(m+gid+8)*K2P + eo + tig + 4], ah[3], al[3]);
        #pragma unroll
        for (int nt = 0; nt < 4; ++nt) {
            int n = wx*32 + nt*8;
            unsigned bh0, bl0, bh1, bl1;
            split_tf32(Bs2[(n+gid)*K2P + eo + tig    ], bh0, bl0);
            split_tf32(Bs2[(n+gid)*K2P + eo + tig + 4], bh1, bl1);
            mma_tf32(acc[nt], ah[0],ah[1],ah[2],ah[3], bh0, bh1);
            mma_tf32(acc[nt], ah[0],ah[1],ah[2],ah[3], bl0, bl1);
            mma_tf32(acc[nt], al[0],al[1],al[2],al[3], bh0, bh1);
        }
    }
    __syncthreads();

    #pragma unroll
    for (int nt = 0; nt < 4; ++nt) {
        int r0 = wy*16 + gid, r1 = r0 + 8;
        int nc = wx*32 + nt*8 + tig*2;
        As2[r0*K2P + nc    ] = acc[nt][0];
        As2[r0*K2P + nc + 1] = acc[nt][1];
        As2[r1*K2P + nc    ] = acc[nt][2];
        As2[r1*K2P + nc + 1] = acc[nt][3];
    }
    __syncthreads();
    #pragma unroll
    for (int p = 0; p < 4; ++p) {
        int idx = tid + p*256;
        int row = idx >> 4, q = idx & 15;
        float4 v = *(const float4*)&As2[row*K2P + q*4];
        *(float4*)(g_C2C + ((size_t)h*SQ + i0 + row)*SQ + j0 + q*4) = v;
    }
}

// ================= K3: pos contraction, tf32 MMA, pair-issue cp.async =====
#define JW3 128                   // j rows per CTA
#define AP3 20                    // smem pitch (floats)
#define ASTG (JW3*AP3)            // 2560 floats per stage
#define BSTG (NC*AP3)             // 480 floats per stage
#define NG3  24                   // issue groups (2 chunks each)
#define EP3 132                   // epilogue [c][j] pitch

__global__ void __launch_bounds__(256, 4) k3_pos(const float* __restrict__ pos)
{
    __shared__ float As[4*ASTG];   // 40 KB
    __shared__ float Bs[4*BSTG];   // 7.5 KB
    int jb = blockIdx.x;           // 0..2
    int i  = blockIdx.y;           // 0..383
    int tid = threadIdx.x;         // 256 = 8 warps
    int warp = tid >> 5, lane = tid & 31;
    int gid = lane >> 2, tig = lane & 3;
    int j0w = warp * 16;

    const float* posi = pos + (size_t)i * (SQ*HDIM) + (size_t)jb * JW3 * HDIM;
    const float* wsrc = g_qkW + (size_t)i * QKW_I_STRIDE;

    float acc[3][4];
    #pragma unroll
    for (int ct = 0; ct < 3; ++ct)
        #pragma unroll
        for (int r = 0; r < 4; ++r) acc[ct][r] = 0.f;

    auto issuePair = [&](int k) {
        int e0 = k * 32;
        int sA = (2*k) & 3;
        float* asb = As + sA*ASTG;
        float* bsb = Bs + sA*BSTG;
        #pragma unroll
        for (int p = 0; p < 4; ++p) {
            int idx = tid + p*256;
            int j = idx >> 3, q = idx & 7;
            cp16(asb + (q>>2)*ASTG + j*AP3 + (q&3)*4,
                 posi + (size_t)j*HDIM + e0 + q*4);
        }
        if (tid < 192) {
            int c = tid >> 3, q = tid & 7;
            cp16(bsb + (q>>2)*BSTG + c*AP3 + (q&3)*4,
                 wsrc + (size_t)c*HDIM + e0 + q*4);
        }
    };

    issuePair(0); cp_commit();
    issuePair(1); cp_commit();

    for (int k = 0; k < NG3; ++k) {
        if (k < NG3-1) cp_wait<1>();
        else           cp_wait<0>();
        __syncthreads();

        #pragma unroll
        for (int half = 0; half < 2; ++half) {
            int s = (2*k + half) & 3;
            const float* a = As + s*ASTG;
            const float* b = Bs + s*BSTG;
            #pragma unroll
            for (int ks = 0; ks < 2; ++ks) {
                int eo = ks * 8;
                unsigned a0 = __float_as_uint(a[(j0w + gid    )*AP3 + eo + tig    ]);
                unsigned a1 = __float_as_uint(a[(j0w + gid + 8)*AP3 + eo + tig    ]);
                unsigned a2 = __float_as_uint(a[(j0w + gid    )*AP3 + eo + tig + 4]);
                unsigned a3 = __float_as_uint(a[(j0w + gid + 8)*AP3 + eo + tig + 4]);
                #pragma unroll
                for (int ct = 0; ct < 3; ++ct) {
                    unsigned b0 = __float_as_uint(b[(ct*8 + gid)*AP3 + eo + tig    ]);
                    unsigned b1 = __float_as_uint(b[(ct*8 + gid)*AP3 + eo + tig + 4]);
                    mma_tf32(acc[ct], a0, a1, a2, a3, b0, b1);
                }
            }
        }
        __syncthreads();
        if (k + 2 < NG3) { issuePair(k + 2); cp_commit(); }
    }

    #pragma unroll
    for (int ct = 0; ct < 3; ++ct) {
        int c = ct*8 + tig*2;
        As[ c   *EP3 + j0w + gid    ] = acc[ct][0];
        As[(c+1)*EP3 + j0w + gid    ] = acc[ct][1];
        As[ c   *EP3 + j0w + gid + 8] = acc[ct][2];
        As[(c+1)*EP3 + j0w + gid + 8] = acc[ct][3];
    }
    __syncthreads();
    float* o_base = g_OUT + (size_t)i * OUT_I_STRIDE + jb*JW3;
    #pragma unroll
    for (int p = 0; p < 3; ++p) {
        int idx = tid + p*256;
        int c = idx >> 5, j4 = (idx & 31) * 4;
        float4 v = *(const float4*)&As[c*EP3 + j4];
        *(float4*)(o_base + c*SQ + j4) = v;
    }
}

// ================= KS: fused scores assembly + softmax ====================
#define SPITCH 386
__global__ void __launch_bounds__(256) ks_fused(const float* __restrict__ mask)
{
    __shared__ float S[16*SPITCH];        // 24.7KB
    int ib = blockIdx.x, h = blockIdx.y;
    int i0 = ib * 16;
    int tid = threadIdx.x;

    #pragma unroll
    for (int p = 0; p < 24; ++p) {
        int idx = tid + p*256;
        int ii = idx / 384, j = idx % 384;
        float v = g_C2C[((size_t)h*SQ + i0 + ii)*SQ + j]
                + g_OUT[(size_t)(i0 + ii)*OUT_I_STRIDE + h*SQ + j]
                + g_kb[h*SQ + j];
        S[ii*SPITCH + j] = v * 0.125f + mask[j];
    }
    __syncthreads();

    {
        int ti = tid & 15, tj = tid >> 4;
        #pragma unroll
        for (int t = 0; t < 24; ++t) {
            int j = t*16 + tj;
            float v = g_OUT[(size_t)j*OUT_I_STRIDE + (12 + h)*SQ + i0 + ti];
            S[ti*SPITCH + j] += v * 0.125f;
        }
    }
    __syncthreads();

    int warp = tid >> 5, lane = tid & 31;
    #pragma unroll
    for (int w2 = 0; w2 < 2; ++w2) {
        int il = warp*2 + w2;
        const float* srow = &S[il*SPITCH];
        float x[12];
        float m = -1e30f;
        #pragma unroll
        for (int t = 0; t < 12; ++t) { x[t] = srow[lane + t*32]; m = fmaxf(m, x[t]); }
        #pragma unroll
        for (int o = 16; o; o >>= 1) m = fmaxf(m, __shfl_xor_sync(0xffffffffu, m, o));
        float ss = 0.f;
        #pragma unroll
        for (int t = 0; t < 12; ++t) { x[t] = __expf(x[t] - m); ss += x[t]; }
        #pragma unroll
        for (int o = 16; o; o >>= 1) ss += __shfl_xor_sync(0xffffffffu, ss, o);
        float inv = 1.f / ss;
        float* prow = g_P + ((size_t)h*SQ + i0 + il)*SQ;
        #pragma unroll
        for (int t = 0; t < 12; ++t) prow[lane + t*32] = x[t] * inv;
    }
}

// ================= K5: context = P @ V^T via 3xTF32 MMA ===================
#define K5P 68
__global__ void __launch_bounds__(256) k5_pv(float* __restrict__ out)
{
    __shared__ float As5[32*K5P];   // [i][k]  8.7 KB
    __shared__ float Bs5[64*K5P];   // [n][k] 17.4 KB
    int ib = blockIdx.x, h = blockIdx.y;
    int i0 = ib * 32;
    int tid = threadIdx.x, warp = tid >> 5, lane = tid & 31;
    int gid = lane >> 2, tig = lane & 3;
    int wy = warp & 1;         // i-tile (16 rows)
    int wx = warp >> 1;        // n-block (16 cols), nt in {0,1}

    float acc[2][4];
    #pragma unroll
    for (int nt = 0; nt < 2; ++nt)
        #pragma unroll
        for (int r = 0; r < 4; ++r) acc[nt][r] = 0.f;

    for (int kc = 0; kc < 6; ++kc) {
        int k0 = kc * 64;
        __syncthreads();
        #pragma unroll
        for (int p = 0; p < 2; ++p) {
            int idx = tid + p*256;
            int row = idx >> 4, q = idx & 15;
            *(float4*)&As5[row*K5P + q*4] =
                *(const float4*)(g_P + ((size_t)h*SQ + i0 + row)*SQ + k0 + q*4);
        }
        #pragma unroll
        for (int p = 0; p < 4; ++p) {
            int idx = tid + p*256;
            int row = idx >> 4, q = idx & 15;
            *(float4*)&Bs5[row*K5P + q*4] =
                *(const float4*)(g_VT + ((size_t)h*64 + row)*SQ + k0 + q*4);
        }
        __syncthreads();

        #pragma unroll
        for (int ks = 0; ks < 8; ++ks) {
            int eo = ks * 8;
            int m = wy * 16;
            unsigned ah[4], al[4];
            split_tf32(As5[(m+gid  )*K5P + eo + tig    ], ah[0], al[0]);
            split_tf32(As5[(m+gid+8)*K5P + eo + tig    ], ah[1], al[1]);
            split_tf32(As5[(m+gid  )*K5P + eo + tig + 4], ah[2], al[2]);
            split_tf32(As5[(m+gid+8)*K5P + eo + tig + 4], ah[3], al[3]);
            #pragma unroll
            for (int nt = 0; nt < 2; ++nt) {
                int n = wx*16 + nt*8;
                unsigned bh0, bl0, bh1, bl1;
                split_tf32(Bs5[(n+gid)*K5P + eo + tig    ], bh0, bl0);
                split_tf32(Bs5[(n+gid)*K5P + eo + tig + 4], bh1, bl1);
                mma_tf32(acc[nt], ah[0],ah[1],ah[2],ah[3], bh0, bh1);
                mma_tf32(acc[nt], ah[0],ah[1],ah[2],ah[3], bl0, bl1);
                mma_tf32(acc[nt], al[0],al[1],al[2],al[3], bh0, bh1);
            }
        }
    }
    __syncthreads();

    #pragma unroll
    for (int nt = 0; nt < 2; ++nt) {
        int r0 = wy*16 + gid, r1 = r0 + 8;
        int nc = wx*16 + nt*8 + tig*2;
        As5[r0*K5P + nc    ] = acc[nt][0];
        As5[r0*K5P + nc + 1] = acc[nt][1];
        As5[r1*K5P + nc    ] = acc[nt][2];
        As5[r1*K5P + nc + 1] = acc[nt][3];
    }
    __syncthreads();
    #pragma unroll
    for (int p = 0; p < 2; ++p) {
        int idx = tid + p*256;
        int row = idx >> 4, q = idx & 15;
        float4 v = *(const float4*)&As5[row*K5P + q*4];
        *(float4*)(out + (size_t)(i0 + row)*HDIM + h*64 + q*4) = v;
    }
}

// ================= launch =================================================
extern "C" void kernel_launch(void* const* d_in, const int* in_sizes, int n_in,
                              void* d_out, int out_size)
{
    const float* hidden = (const float*)d_in[0];
    const float* mask   = (const float*)d_in[1];
    const float* pos    = (const float*)d_in[2];
    const float* Wq  = (const float*)d_in[3];
    const float* bq  = (const float*)d_in[4];
    const float* Wk  = (const float*)d_in[5];
    const float* bk  = (const float*)d_in[6];
    const float* Wv  = (const float*)d_in[7];
    const float* bv  = (const float*)d_in[8];
    const float* Wpk = (const float*)d_in[9];
    // d_in[10] = bpk: constant over j -> softmax-invariant -> cancels exactly
    const float* Wpq = (const float*)d_in[11];
    const float* bpq = (const float*)d_in[12];
    float* out = (float*)d_out;

    // k1_qkv kept in the sampled 4th slot to verify the grid fix.
    kT_transpose<<<dim3(24, 24), 256>>>(Wq, 0);
    kT_transpose<<<dim3(24, 24), 256>>>(Wk, 1);
    kT_transpose<<<dim3(24, 24), 256>>>(Wv, 2);
    k1_qkv<<<dim3(12, 12, 3), 256>>>(hidden, bq, bk, bv);
    k1b_kb<<<12, 384>>>(bpq);
    k2_qkw<<<dim3(6, 24, 6), 256>>>(Wpk, Wpq);
    k3_pos<<<dim3(3, 384), 256>>>(pos);
    k2b_c2c<<<dim3(6, 6, 12), 256>>>();
    ks_fused<<<dim3(24, 12), 256>>>(mask);
    k5_pv<<<dim3(12, 12), 256>>>(out);
}

// round 16
// speedup vs baseline: 1.0983x; 1.0953x over previous
#include <cuda_runtime.h>
#include <math.h>

#define SQ 384
#define HDIM 768
#define NHEAD 12
#define DH 64
#define NC 24
#define QKW_I_STRIDE (NC*HDIM)   // 18432
#define OUT_I_STRIDE (NC*SQ)     // 9216

// ---------------- scratch (device globals; no allocation allowed) ----------
__device__ float g_Q[NHEAD*SQ*DH];
__device__ float g_K[NHEAD*SQ*DH];
__device__ float g_VT[NHEAD*DH*SQ];      // [h][d][j]  (V transposed, bias added)
__device__ float g_kb[NHEAD*SQ];
__device__ float g_WT[3*HDIM*HDIM];      // [z][n][k] = W_z[k][n] transposed
__device__ float g_qkW[SQ*NC*HDIM];      // [i][c][e]
__device__ float g_OUT[SQ*NC*SQ];        // [i][c][j]
__device__ float g_C2C[NHEAD*SQ*SQ];     // [h][i][j]
__device__ float g_P[NHEAD*SQ*SQ];       // probs

__device__ __forceinline__ void mma_tf32(float* d, unsigned a0, unsigned a1,
                                         unsigned a2, unsigned a3,
                                         unsigned b0, unsigned b1) {
    asm volatile(
        "mma.sync.aligned.m16n8k8.row.col.f32.tf32.tf32.f32 "
        "{%0,%1,%2,%3}, {%4,%5,%6,%7}, {%8,%9}, {%0,%1,%2,%3};"
        : "+f"(d[0]), "+f"(d[1]), "+f"(d[2]), "+f"(d[3])
        : "r"(a0), "r"(a1), "r"(a2), "r"(a3), "r"(b0), "r"(b1));
}

// split fp32 into tf32 hi + tf32 lo (3xTF32 error compensation)
__device__ __forceinline__ void split_tf32(float x, unsigned& hi, unsigned& lo) {
    unsigned h;
    asm("cvt.rna.tf32.f32 %0, %1;" : "=r"(h) : "f"(x));
    float r = x - __uint_as_float(h);
    unsigned l;
    asm("cvt.rna.tf32.f32 %0, %1;" : "=r"(l) : "f"(r));
    hi = h; lo = l;
}

__device__ __forceinline__ void cp16(void* dst_smem, const void* src_gmem) {
    unsigned d = (unsigned)__cvta_generic_to_shared(dst_smem);
    asm volatile("cp.async.ca.shared.global [%0], [%1], 16;" :: "r"(d), "l"(src_gmem));
}
__device__ __forceinline__ void cp_commit() {
    asm volatile("cp.async.commit_group;");
}
template <int N>
__device__ __forceinline__ void cp_wait() {
    asm volatile("cp.async.wait_group %0;" :: "n"(N));
}

// ================= KT: transpose Wq/Wk/Wv -> g_WT[z][n][k] ================
__global__ void kT_transpose(const float* __restrict__ Wq,
                             const float* __restrict__ Wk,
                             const float* __restrict__ Wv)
{
    __shared__ float t[32][33];
    int z = blockIdx.z;
    const float* W = (z==0) ? Wq : (z==1) ? Wk : Wv;
    float* WT = g_WT + (size_t)z*HDIM*HDIM;
    int n0 = blockIdx.x*32, k0 = blockIdx.y*32;
    int tx = threadIdx.x & 31, ty = threadIdx.x >> 5;   // 256 thr: ty 0..7
    #pragma unroll
    for (int r = 0; r < 32; r += 8)
        t[ty+r][tx] = W[(size_t)(k0+ty+r)*HDIM + n0 + tx];
    __syncthreads();
    #pragma unroll
    for (int r = 0; r < 32; r += 8)
        WT[(size_t)(n0+ty+r)*HDIM + k0 + tx] = t[tx][ty+r];
}

// ================= K1: QKV projections, 3xTF32 MMA + cp.async pipeline ====
// (round-13 proven structure; + fused kb for z==1, dead g_V store removed)
#define K1AP 20
#define K1ASTG (64*K1AP)     // 1280 floats per stage
#define K1NG 24              // 768 / 32 k per group

__global__ void __launch_bounds__(256, 4) k1_qkv(const float* __restrict__ hidden,
                       const float* __restrict__ bq,
                       const float* __restrict__ bk,
                       const float* __restrict__ bv,
                       const float* __restrict__ bpq)
{
    __shared__ float As[4*K1ASTG];    // 20.5 KB (epilogue reuses: 64*68=4352 fl)
    __shared__ float Bs4[4*K1ASTG];   // 20.5 KB
    int h = blockIdx.x, ib = blockIdx.y, z = blockIdx.z;
    const float* b = (z==0) ? bq : (z==1) ? bk : bv;
    float* outp    = (z==0) ? g_Q : g_K;      // z==2 writes only g_VT
    int i0 = ib * 64;
    int tid = threadIdx.x, warp = tid >> 5, lane = tid & 31;
    int gid = lane >> 2, tig = lane & 3;
    int wy = warp & 3;        // i-tile (16 rows)
    int wx = warp >> 2;       // n-half (32 cols)

    const float* abase = hidden + (size_t)i0*HDIM;
    const float* bbase = g_WT + (size_t)z*HDIM*HDIM + (size_t)(h*64)*HDIM;

    float acc[4][4];
    #pragma unroll
    for (int nt = 0; nt < 4; ++nt)
        #pragma unroll
        for (int r = 0; r < 4; ++r) acc[nt][r] = 0.f;

    auto issuePair = [&](int k) {
        int e0 = k * 32;
        int sA = (2*k) & 3;
        float* as = As  + sA*K1ASTG;
        float* bs = Bs4 + sA*K1ASTG;
        #pragma unroll
        for (int p = 0; p < 2; ++p) {
            int idx = tid + p*256;
            int r = idx >> 3, q = idx & 7;
            cp16(as + (q>>2)*K1ASTG + r*K1AP + (q&3)*4, abase + (size_t)r*HDIM + e0 + q*4);
        }
        #pragma unroll
        for (int p = 0; p < 2; ++p) {
            int idx = tid + p*256;
            int r = idx >> 3, q = idx & 7;
            cp16(bs + (q>>2)*K1ASTG + r*K1AP + (q&3)*4, bbase + (size_t)r*HDIM + e0 + q*4);
        }
    };

    issuePair(0); cp_commit();
    issuePair(1); cp_commit();

    for (int k = 0; k < K1NG; ++k) {
        if (k < K1NG-1) cp_wait<1>(); else cp_wait<0>();
        __syncthreads();
        #pragma unroll
        for (int half = 0; half < 2; ++half) {
            int s = (2*k + half) & 3;
            const float* a   = As  + s*K1ASTG;
            const float* bsm = Bs4 + s*K1ASTG;
            #pragma unroll
            for (int ks = 0; ks < 2; ++ks) {
                int eo = ks * 8;
                int m = wy * 16;
                unsigned ah[4], al[4];
                split_tf32(a[(m+gid  )*K1AP + eo + tig    ], ah[0], al[0]);
                split_tf32(a[(m+gid+8)*K1AP + eo + tig    ], ah[1], al[1]);
                split_tf32(a[(m+gid  )*K1AP + eo + tig + 4], ah[2], al[2]);
                split_tf32(a[(m+gid+8)*K1AP + eo + tig + 4], ah[3], al[3]);
                #pragma unroll
                for (int nt = 0; nt < 4; ++nt) {
                    int n = wx*32 + nt*8;
                    unsigned bh0, bl0, bh1, bl1;
                    split_tf32(bsm[(n+gid)*K1AP + eo + tig    ], bh0, bl0);
                    split_tf32(bsm[(n+gid)*K1AP + eo + tig + 4], bh1, bl1);
                    mma_tf32(acc[nt], ah[0],ah[1],ah[2],ah[3], bh0, bh1);
                    mma_tf32(acc[nt], ah[0],ah[1],ah[2],ah[3], bl0, bl1);
                    mma_tf32(acc[nt], al[0],al[1],al[2],al[3], bh0, bh1);
                }
            }
        }
        __syncthreads();
        if (k + 2 < K1NG) { issuePair(k + 2); cp_commit(); }
    }

    // epilogue: stage [i][n] (pitch 68, reuse As)
    #pragma unroll
    for (int nt = 0; nt < 4; ++nt) {
        int r0 = wy*16 + gid, r1 = r0 + 8;
        int nc = wx*32 + nt*8 + tig*2;
        As[r0*68 + nc    ] = acc[nt][0];
        As[r0*68 + nc + 1] = acc[nt][1];
        As[r1*68 + nc    ] = acc[nt][2];
        As[r1*68 + nc + 1] = acc[nt][3];
    }
    __syncthreads();
    if (z != 2) {
        // Q / K: add bias, coalesced STG
        #pragma unroll
        for (int p = 0; p < 4; ++p) {
            int idx = tid + p*256;
            int row = idx >> 4, q = idx & 15;
            float4 v  = *(const float4*)&As[row*68 + q*4];
            float4 bb = *(const float4*)&b[h*64 + q*4];
            v.x += bb.x; v.y += bb.y; v.z += bb.z; v.w += bb.w;
            *(float4*)(outp + (size_t)(h*SQ + i0 + row)*DH + q*4) = v;
        }
    } else {
        // V: write ONLY the transposed copy (g_V itself is never read)
        #pragma unroll
        for (int p = 0; p < 16; ++p) {
            int idx = tid + p*256;          // 4096 = 64n * 64i
            int n = idx >> 6, ii = idx & 63;
            g_VT[(size_t)(h*64 + n)*SQ + i0 + ii] = As[ii*68 + n] + b[h*64 + n];
        }
    }
    // fused k1b: kb[h][i] = (K[h,i,:] incl bias) . bpq_h   (z == 1 only)
    if (z == 1) {
        int row = tid >> 2, part = tid & 3;     // 64 rows x 4 threads
        const float* bp = bpq + h*64;
        float s = 0.f;
        #pragma unroll
        for (int u = 0; u < 16; ++u) {
            int n = part*16 + u;
            s += (As[row*68 + n] + b[h*64 + n]) * bp[n];
        }
        s += __shfl_xor_sync(0xffffffffu, s, 1);
        s += __shfl_xor_sync(0xffffffffu, s, 2);
        if (part == 0) g_kb[h*SQ + i0 + row] = s;
    }
}

// ================= K2: qkW[i][c][e], 3xTF32, single-split + middle grid ===
#define K2P 68    // smem pitch; 68 mod 32 == 4 -> conflict-free fragments
__global__ void __launch_bounds__(256) k2_qkw(const float* __restrict__ Wpk,
                                              const float* __restrict__ Wpq)
{
    __shared__ float Asr[64*K2P];   // raw A [i][d]      17.4 KB
    __shared__ float Bhi[32*K2P];   // B hi  [e][d]       8.7 KB
    __shared__ float Blo[32*K2P];   // B lo  [e][d]       8.7 KB
    int ib  = blockIdx.x;           // 0..5
    int c   = blockIdx.y;           // 0..23
    int ebg = blockIdx.z;           // 0..5 (4 eb-tiles each)
    int h  = (c < 12) ? c : c - 12;
    const float* Asrc = (c < 12) ? g_Q : g_K;
    const float* Wp   = (c < 12) ? Wpk : Wpq;
    int i0 = ib * 64;
    int tid = threadIdx.x, warp = tid >> 5, lane = tid & 31;
    int gid = lane >> 2, tig = lane & 3;
    int wy = warp & 3;              // 4 i-tiles of 16 rows
    int wx = warp >> 2;             // 2 e-halves of 16 cols
    int m  = wy * 16;

    #pragma unroll
    for (int p = 0; p < 4; ++p) {
        int idx = tid + p*256;
        int row = idx >> 4, q = idx & 15;
        *(float4*)&Asr[row*K2P + q*4] =
            *(const float4*)(Asrc + (size_t)(h*SQ + i0 + row)*DH + q*4);
    }
    __syncthreads();

    unsigned ah[8][4], al[8][4];
    #pragma unroll
    for (int ks = 0; ks < 8; ++ks) {
        int eo = ks * 8;
        split_tf32(Asr[(m+gid  )*K2P + eo + tig    ], ah[ks][0], al[ks][0]);
        split_tf32(Asr[(m+gid+8)*K2P + eo + tig    ], ah[ks][1], al[ks][1]);
        split_tf32(Asr[(m+gid  )*K2P + eo + tig + 4], ah[ks][2], al[ks][2]);
        split_tf32(Asr[(m+gid+8)*K2P + eo + tig + 4], ah[ks][3], al[ks][3]);
    }

    float4 rb[2];
    auto loadB = [&](int e0) {
        #pragma unroll
        for (int p = 0; p < 2; ++p) {
            int idx = tid + p*256;
            int row = idx >> 4, q = idx & 15;
            rb[p] = *(const float4*)(Wp + (size_t)(e0 + row)*HDIM + h*64 + q*4);
        }
    };
    int eb0 = ebg * 4;
    loadB(eb0 * 32);

    for (int t = 0; t < 4; ++t) {
        int eb = eb0 + t;
        #pragma unroll
        for (int p = 0; p < 2; ++p) {
            int idx = tid + p*256;
            int row = idx >> 4, q = idx & 15;
            float4 v = rb[p];
            unsigned h0,l0,h1,l1,h2,l2,h3,l3;
            split_tf32(v.x, h0, l0); split_tf32(v.y, h1, l1);
            split_tf32(v.z, h2, l2); split_tf32(v.w, h3, l3);
            float4 hv = make_float4(__uint_as_float(h0), __uint_as_float(h1),
                                    __uint_as_float(h2), __uint_as_float(h3));
            float4 lv = make_float4(__uint_as_float(l0), __uint_as_float(l1),
                                    __uint_as_float(l2), __uint_as_float(l3));
            *(float4*)&Bhi[row*K2P + q*4] = hv;
            *(float4*)&Blo[row*K2P + q*4] = lv;
        }
        if (t + 1 < 4) loadB((eb + 1) * 32);
        __syncthreads();

        float acc[2][4];
        #pragma unroll
        for (int nt = 0; nt < 2; ++nt)
            #pragma unroll
            for (int r = 0; r < 4; ++r) acc[nt][r] = 0.f;

        #pragma unroll
        for (int ks = 0; ks < 8; ++ks) {
            int eo = ks * 8;
            #pragma unroll
            for (int nt = 0; nt < 2; ++nt) {
                int n = wx*16 + nt*8;
                unsigned bh0 = __float_as_uint(Bhi[(n+gid)*K2P + eo + tig    ]);
                unsigned bh1 = __float_as_uint(Bhi[(n+gid)*K2P + eo + tig + 4]);
                unsigned bl0 = __float_as_uint(Blo[(n+gid)*K2P + eo + tig    ]);
                unsigned bl1 = __float_as_uint(Blo[(n+gid)*K2P + eo + tig + 4]);
                mma_tf32(acc[nt], ah[ks][0],ah[ks][1],ah[ks][2],ah[ks][3], bh0, bh1);
                mma_tf32(acc[nt], ah[ks][0],ah[ks][1],ah[ks][2],ah[ks][3], bl0, bl1);
                mma_tf32(acc[nt], al[ks][0],al[ks][1],al[ks][2],al[ks][3], bh0, bh1);
            }
        }

        int e0 = eb * 32;
        #pragma unroll
        for (int nt = 0; nt < 2; ++nt) {
            int n = wx*16 + nt*8;
            float* o0 = g_qkW + (size_t)(i0 + m + gid    )*QKW_I_STRIDE + c*HDIM + e0 + n + tig*2;
            float* o1 = g_qkW + (size_t)(i0 + m + gid + 8)*QKW_I_STRIDE + c*HDIM + e0 + n + tig*2;
            *(float2*)o0 = make_float2(acc[nt][0], acc[nt][1]);
            *(float2*)o1 = make_float2(acc[nt][2], acc[nt][3]);
        }
        __syncthreads();
    }
}

// ================= K2b: c2c[h][i][j], 3xTF32 MMA ==========================
__global__ void __launch_bounds__(256) k2b_c2c()
{
    __shared__ float As2[64*K2P];
    __shared__ float Bs2[64*K2P];
    int jb = blockIdx.x, ib = blockIdx.y, h = blockIdx.z;
    int i0 = ib*64, j0 = jb*64;
    int tid = threadIdx.x, warp = tid >> 5, lane = tid & 31;
    int gid = lane >> 2, tig = lane & 3;
    int wy = warp & 3, wx = warp >> 2;

    #pragma unroll
    for (int p = 0; p < 4; ++p) {
        int idx = tid + p*256;
        int row = idx >> 4, q = idx & 15;
        *(float4*)&As2[row*K2P + q*4] = *(const float4*)(g_Q + (size_t)(h*SQ + i0 + row)*DH + q*4);
        *(float4*)&Bs2[row*K2P + q*4] = *(const float4*)(g_K + (size_t)(h*SQ + j0 + row)*DH + q*4);
    }
    __syncthreads();

    float acc[4][4];
    #pragma unroll
    for (int nt = 0; nt < 4; ++nt)
        #pragma unroll
        for (int r = 0; r < 4; ++r) acc[nt][r] = 0.f;

    #pragma unroll
    for (int ks = 0; ks < 8; ++ks) {
        int eo = ks * 8;
        int m = wy * 16;
        unsigned ah[4], al[4];
        split_tf32(As2[(m+gid  )*K2P + eo + tig    ], ah[0], al[0]);
        split_tf32(As2[(m+gid+8)*K2P + eo + tig    ], ah[1], al[1]);
        split_tf32(As2[(m+gid  )*K2P + eo + tig + 4], ah[2], al[2]);
        split_tf32(As2[(m+gid+8)*K2P + eo + tig + 4], ah[3], al[3]);
        #pragma unroll
        for (int nt = 0; nt < 4; ++nt) {
            int n = wx*32 + nt*8;
            unsigned bh0, bl0, bh1, bl1;
            split_tf32(Bs2[(n+gid)*K2P + eo + tig    ], bh0, bl0);
            split_tf32(Bs2[(n+gid)*K2P + eo + tig + 4], bh1, bl1);
            mma_tf32(acc[nt], ah[0],ah[1],ah[2],ah[3], bh0, bh1);
            mma_tf32(acc[nt], ah[0],ah[1],ah[2],ah[3], bl0, bl1);
            mma_tf32(acc[nt], al[0],al[1],al[2],al[3], bh0, bh1);
        }
    }
    __syncthreads();

    #pragma unroll
    for (int nt = 0; nt < 4; ++nt) {
        int r0 = wy*16 + gid, r1 = r0 + 8;
        int nc = wx*32 + nt*8 + tig*2;
        As2[r0*K2P + nc    ] = acc[nt][0];
        As2[r0*K2P + nc + 1] = acc[nt][1];
        As2[r1*K2P + nc    ] = acc[nt][2];
        As2[r1*K2P + nc + 1] = acc[nt][3];
    }
    __syncthreads();
    #pragma unroll
    for (int p = 0; p < 4; ++p) {
        int idx = tid + p*256;
        int row = idx >> 4, q = idx & 15;
        float4 v = *(const float4*)&As2[row*K2P + q*4];
        *(float4*)(g_C2C + ((size_t)h*SQ + i0 + row)*SQ + j0 + q*4) = v;
    }
}

// ================= K3: pos contraction, tf32 MMA, pair-issue cp.async =====
#define JW3 128                   // j rows per CTA
#define AP3 20                    // smem pitch (floats)
#define ASTG (JW3*AP3)            // 2560 floats per stage
#define BSTG (NC*AP3)             // 480 floats per stage
#define NG3  24                   // issue groups (2 chunks each)
#define EP3 132                   // epilogue [c][j] pitch

__global__ void __launch_bounds__(256, 4) k3_pos(const float* __restrict__ pos)
{
    __shared__ float As[4*ASTG];   // 40 KB
    __shared__ float Bs[4*BSTG];   // 7.5 KB
    int jb = blockIdx.x;           // 0..2
    int i  = blockIdx.y;           // 0..383
    int tid = threadIdx.x;         // 256 = 8 warps
    int warp = tid >> 5, lane = tid & 31;
    int gid = lane >> 2, tig = lane & 3;
    int j0w = warp * 16;

    const float* posi = pos + (size_t)i * (SQ*HDIM) + (size_t)jb * JW3 * HDIM;
    const float* wsrc = g_qkW + (size_t)i * QKW_I_STRIDE;

    float acc[3][4];
    #pragma unroll
    for (int ct = 0; ct < 3; ++ct)
        #pragma unroll
        for (int r = 0; r < 4; ++r) acc[ct][r] = 0.f;

    auto issuePair = [&](int k) {
        int e0 = k * 32;
        int sA = (2*k) & 3;
        float* asb = As + sA*ASTG;
        float* bsb = Bs + sA*BSTG;
        #pragma unroll
        for (int p = 0; p < 4; ++p) {
            int idx = tid + p*256;
            int j = idx >> 3, q = idx & 7;
            cp16(asb + (q>>2)*ASTG + j*AP3 + (q&3)*4,
                 posi + (size_t)j*HDIM + e0 + q*4);
        }
        if (tid < 192) {
            int c = tid >> 3, q = tid & 7;
            cp16(bsb + (q>>2)*BSTG + c*AP3 + (q&3)*4,
                 wsrc + (size_t)c*HDIM + e0 + q*4);
        }
    };

    issuePair(0); cp_commit();
    issuePair(1); cp_commit();

    for (int k = 0; k < NG3; ++k) {
        if (k < NG3-1) cp_wait<1>();
        else           cp_wait<0>();
        __syncthreads();

        #pragma unroll
        for (int half = 0; half < 2; ++half) {
            int s = (2*k + half) & 3;
            const float* a = As + s*ASTG;
            const float* b = Bs + s*BSTG;
            #pragma unroll
            for (int ks = 0; ks < 2; ++ks) {
                int eo = ks * 8;
                unsigned a0 = __float_as_uint(a[(j0w + gid    )*AP3 + eo + tig    ]);
                unsigned a1 = __float_as_uint(a[(j0w + gid + 8)*AP3 + eo + tig    ]);
                unsigned a2 = __float_as_uint(a[(j0w + gid    )*AP3 + eo + tig + 4]);
                unsigned a3 = __float_as_uint(a[(j0w + gid + 8)*AP3 + eo + tig + 4]);
                #pragma unroll
                for (int ct = 0; ct < 3; ++ct) {
                    unsigned b0 = __float_as_uint(b[(ct*8 + gid)*AP3 + eo + tig    ]);
                    unsigned b1 = __float_as_uint(b[(ct*8 + gid)*AP3 + eo + tig + 4]);
                    mma_tf32(acc[ct], a0, a1, a2, a3, b0, b1);
                }
            }
        }
        __syncthreads();
        if (k + 2 < NG3) { issuePair(k + 2); cp_commit(); }
    }

    #pragma unroll
    for (int ct = 0; ct < 3; ++ct) {
        int c = ct*8 + tig*2;
        As[ c   *EP3 + j0w + gid    ] = acc[ct][0];
        As[(c+1)*EP3 + j0w + gid    ] = acc[ct][1];
        As[ c   *EP3 + j0w + gid + 8] = acc[ct][2];
        As[(c+1)*EP3 + j0w + gid + 8] = acc[ct][3];
    }
    __syncthreads();
    float* o_base = g_OUT + (size_t)i * OUT_I_STRIDE + jb*JW3;
    #pragma unroll
    for (int p = 0; p < 3; ++p) {
        int idx = tid + p*256;
        int c = idx >> 5, j4 = (idx & 31) * 4;
        float4 v = *(const float4*)&As[c*EP3 + j4];
        *(float4*)(o_base + c*SQ + j4) = v;
    }
}

// ================= KS: fused scores assembly + softmax ====================
#define SPITCH 386
__global__ void __launch_bounds__(256) ks_fused(const float* __restrict__ mask)
{
    __shared__ float S[16*SPITCH];        // 24.7KB
    int ib = blockIdx.x, h = blockIdx.y;
    int i0 = ib * 16;
    int tid = threadIdx.x;

    #pragma unroll
    for (int p = 0; p < 24; ++p) {
        int idx = tid + p*256;
        int ii = idx / 384, j = idx % 384;
        float v = g_C2C[((size_t)h*SQ + i0 + ii)*SQ + j]
                + g_OUT[(size_t)(i0 + ii)*OUT_I_STRIDE + h*SQ + j]
                + g_kb[h*SQ + j];
        S[ii*SPITCH + j] = v * 0.125f + mask[j];
    }
    __syncthreads();

    {
        int ti = tid & 15, tj = tid >> 4;
        #pragma unroll
        for (int t = 0; t < 24; ++t) {
            int j = t*16 + tj;
            float v = g_OUT[(size_t)j*OUT_I_STRIDE + (12 + h)*SQ + i0 + ti];
            S[ti*SPITCH + j] += v * 0.125f;
        }
    }
    __syncthreads();

    int warp = tid >> 5, lane = tid & 31;
    #pragma unroll
    for (int w2 = 0; w2 < 2; ++w2) {
        int il = warp*2 + w2;
        const float* srow = &S[il*SPITCH];
        float x[12];
        float m = -1e30f;
        #pragma unroll
        for (int t = 0; t < 12; ++t) { x[t] = srow[lane + t*32]; m = fmaxf(m, x[t]); }
        #pragma unroll
        for (int o = 16; o; o >>= 1) m = fmaxf(m, __shfl_xor_sync(0xffffffffu, m, o));
        float ss = 0.f;
        #pragma unroll
        for (int t = 0; t < 12; ++t) { x[t] = __expf(x[t] - m); ss += x[t]; }
        #pragma unroll
        for (int o = 16; o; o >>= 1) ss += __shfl_xor_sync(0xffffffffu, ss, o);
        float inv = 1.f / ss;
        float* prow = g_P + ((size_t)h*SQ + i0 + il)*SQ;
        #pragma unroll
        for (int t = 0; t < 12; ++t) prow[lane + t*32] = x[t] * inv;
    }
}

// ================= K5: context = P @ V^T via 3xTF32 MMA ===================
#define K5P 68
__global__ void __launch_bounds__(256) k5_pv(float* __restrict__ out)
{
    __shared__ float As5[32*K5P];   // [i][k]  8.7 KB
    __shared__ float Bs5[64*K5P];   // [n][k] 17.4 KB
    int ib = blockIdx.x, h = blockIdx.y;
    int i0 = ib * 32;
    int tid = threadIdx.x, warp = tid >> 5, lane = tid & 31;
    int gid = lane >> 2, tig = lane & 3;
    int wy = warp & 1;         // i-tile (16 rows)
    int wx = warp >> 1;        // n-block (16 cols), nt in {0,1}

    float acc[2][4];
    #pragma unroll
    for (int nt = 0; nt < 2; ++nt)
        #pragma unroll
        for (int r = 0; r < 4; ++r) acc[nt][r] = 0.f;

    for (int kc = 0; kc < 6; ++kc) {
        int k0 = kc * 64;
        __syncthreads();
        #pragma unroll
        for (int p = 0; p < 2; ++p) {
            int idx = tid + p*256;
            int row = idx >> 4, q = idx & 15;
            *(float4*)&As5[row*K5P + q*4] =
                *(const float4*)(g_P + ((size_t)h*SQ + i0 + row)*SQ + k0 + q*4);
        }
        #pragma unroll
        for (int p = 0; p < 4; ++p) {
            int idx = tid + p*256;
            int row = idx >> 4, q = idx & 15;
            *(float4*)&Bs5[row*K5P + q*4] =
                *(const float4*)(g_VT + ((size_t)h*64 + row)*SQ + k0 + q*4);
        }
        __syncthreads();

        #pragma unroll
        for (int ks = 0; ks < 8; ++ks) {
            int eo = ks * 8;
            int m = wy * 16;
            unsigned ah[4], al[4];
            split_tf32(As5[(m+gid  )*K5P + eo + tig    ], ah[0], al[0]);
            split_tf32(As5[(m+gid+8)*K5P + eo + tig    ], ah[1], al[1]);
            split_tf32(As5[(m+gid  )*K5P + eo + tig + 4], ah[2], al[2]);
            split_tf32(As5[(m+gid+8)*K5P + eo + tig + 4], ah[3], al[3]);
            #pragma unroll
            for (int nt = 0; nt < 2; ++nt) {
                int n = wx*16 + nt*8;
                unsigned bh0, bl0, bh1, bl1;
                split_tf32(Bs5[(n+gid)*K5P + eo + tig    ], bh0, bl0);
                split_tf32(Bs5[(n+gid)*K5P + eo + tig + 4], bh1, bl1);
                mma_tf32(acc[nt], ah[0],ah[1],ah[2],ah[3], bh0, bh1);
                mma_tf32(acc[nt], ah[0],ah[1],ah[2],ah[3], bl0, bl1);
                mma_tf32(acc[nt], al[0],al[1],al[2],al[3], bh0, bh1);
            }
        }
    }
    __syncthreads();

    #pragma unroll
    for (int nt = 0; nt < 2; ++nt) {
        int r0 = wy*16 + gid, r1 = r0 + 8;
        int nc = wx*16 + nt*8 + tig*2;
        As5[r0*K5P + nc    ] = acc[nt][0];
        As5[r0*K5P + nc + 1] = acc[nt][1];
        As5[r1*K5P + nc    ] = acc[nt][2];
        As5[r1*K5P + nc + 1] = acc[nt][3];
    }
    __syncthreads();
    #pragma unroll
    for (int p = 0; p < 2; ++p) {
        int idx = tid + p*256;
        int row = idx >> 4, q = idx & 15;
        float4 v = *(const float4*)&As5[row*K5P + q*4];
        *(float4*)(out + (size_t)(i0 + row)*HDIM + h*64 + q*4) = v;
    }
}

// ================= launch =================================================
extern "C" void kernel_launch(void* const* d_in, const int* in_sizes, int n_in,
                              void* d_out, int out_size)
{
    const float* hidden = (const float*)d_in[0];
    const float* mask   = (const float*)d_in[1];
    const float* pos    = (const float*)d_in[2];
    const float* Wq  = (const float*)d_in[3];
    const float* bq  = (const float*)d_in[4];
    const float* Wk  = (const float*)d_in[5];
    const float* bk  = (const float*)d_in[6];
    const float* Wv  = (const float*)d_in[7];
    const float* bv  = (const float*)d_in[8];
    const float* Wpk = (const float*)d_in[9];
    // d_in[10] = bpk: constant over j -> softmax-invariant -> cancels exactly
    const float* Wpq = (const float*)d_in[11];
    const float* bpq = (const float*)d_in[12];
    float* out = (float*)d_out;

    // k3_pos in the sampled 4th slot (confirm unchanged profile).
    kT_transpose<<<dim3(24, 24, 3), 256>>>(Wq, Wk, Wv);
    k1_qkv<<<dim3(12, 6, 3), 256>>>(hidden, bq, bk, bv, bpq);
    k2_qkw<<<dim3(6, 24, 6), 256>>>(Wpk, Wpq);
    k3_pos<<<dim3(3, 384), 256>>>(pos);
    k2b_c2c<<<dim3(6, 6, 12), 256>>>();
    ks_fused<<<dim3(24, 12), 256>>>(mask);
    k5_pv<<<dim3(12, 12), 256>>>(out);
}